// round 16
// baseline (speedup 1.0000x reference)
#include <cuda_runtime.h>
#include <math.h>
#include <stdint.h>

#define T_LEN 8192
#define HALF  4096
#define CH    128
#define BATCH 16
#define NSIG  (BATCH * CH)

#define KSPLIT 16
#define KC     32                          // fp32 per chunk = 128 B rows
#define NCHUNK ((T_LEN / KSPLIT) / KC)     // 16
#define ROWB   144                         // 128B data + 16B pad (conflict-free)
#define BOFF   (128 * ROWB)                // 18432
#define BUFB   (2 * 128 * ROWB)            // 36864 per buffer
#define CHCH   (CH * CH)

// Scratch (alloc-free rule: __device__ globals)
__device__ float g_c[(size_t)BATCH * CH * T_LEN];             // cos(phase): 64 MB
__device__ float g_s[(size_t)BATCH * CH * T_LEN];             // sin(phase): 64 MB
__device__ float g_gram[(size_t)KSPLIT * BATCH * 3 * CH * CH];// tiles: 50 MB

// ===========================================================================
// PTX helpers
// ===========================================================================
__device__ __forceinline__ uint32_t smem_u32(const void* p) {
    uint32_t a;
    asm("{ .reg .u64 t; cvta.to.shared.u64 t, %1; cvt.u32.u64 %0, t; }"
        : "=r"(a) : "l"(p));
    return a;
}
__device__ __forceinline__ void mma_tf32(float* d, const uint32_t* a,
                                         const uint32_t* b) {
    asm volatile(
        "mma.sync.aligned.m16n8k8.row.col.f32.tf32.tf32.f32 "
        "{%0,%1,%2,%3}, {%4,%5,%6,%7}, {%8,%9}, {%0,%1,%2,%3};"
        : "+f"(d[0]), "+f"(d[1]), "+f"(d[2]), "+f"(d[3])
        : "r"(a[0]), "r"(a[1]), "r"(a[2]), "r"(a[3]), "r"(b[0]), "r"(b[1]));
}
__device__ __forceinline__ void cp16(uint32_t smem, const void* g) {
    asm volatile("cp.async.cg.shared.global [%0], [%1], 16;"
                 :: "r"(smem), "l"(g) : "memory");
}
#define CP_COMMIT() asm volatile("cp.async.commit_group;" ::: "memory")
#define CP_WAIT1()  asm volatile("cp.async.wait_group 1;" ::: "memory")
#define CP_WAIT0()  asm volatile("cp.async.wait_group 0;" ::: "memory")
__device__ __forceinline__ uint32_t lds32(uint32_t addr) {
    uint32_t v;
    asm volatile("ld.shared.b32 %0, [%1];" : "=r"(v) : "r"(addr));
    return v;
}
__device__ __forceinline__ uint32_t f2tf32(float f) {
    uint32_t u;
    asm("cvt.rna.tf32.f32 %0, %1;" : "=r"(u) : "f"(f));
    return u;
}

// ===========================================================================
// Kernel 1: two-channel real-packed FFT, single inverse chain (R15, unchanged)
// ===========================================================================
__device__ __forceinline__ int swz(int i) { return i ^ ((i >> 5) & 31); }

template<int P, int LB, int FWD>
__device__ __forceinline__ void stage_one(float2 v[16], int base,
                                          const float2* __restrict__ tw) {
    const int s  = P + LB;
    const int bm = base & ((1 << s) - 1);
    float2 wc[(LB < 3) ? (1 << LB) : 1];
    if (LB < 3) {
#pragma unroll
        for (int q = 0; q < (1 << LB); q++)
            wc[q] = tw[(bm + (q << P)) << (12 - s)];
    }
#pragma unroll
    for (int rr = 0; rr < 16; rr++) {
        if ((rr >> LB) & 1) continue;
        const int r1 = rr | (1 << LB);
        float2 w;
        if (LB < 3) w = wc[rr & ((1 << LB) - 1)];
        else        w = tw[(bm + ((rr & 7) << P)) << (12 - s)];
        float2 a = v[rr], b = v[r1];
        if (FWD) {
            v[rr] = make_float2(a.x + b.x, a.y + b.y);
            float2 d = make_float2(a.x - b.x, a.y - b.y);
            v[r1] = make_float2(d.x * w.x - d.y * w.y, d.x * w.y + d.y * w.x);
        } else {
            float2 tt = make_float2(b.x * w.x + b.y * w.y, b.y * w.x - b.x * w.y);
            v[rr] = make_float2(a.x + tt.x, a.y + tt.y);
            v[r1] = make_float2(a.x - tt.x, a.y - tt.y);
        }
    }
}

template<int P, int FWD, int LBLO, int LBHI>
__device__ __forceinline__ void stages(float2 v[16], int base,
                                       const float2* __restrict__ tw) {
    if (FWD) {
        if (LBHI >= 3 && 3 >= LBLO) stage_one<P, 3, 1>(v, base, tw);
        if (LBHI >= 2 && 2 >= LBLO) stage_one<P, 2, 1>(v, base, tw);
        if (LBHI >= 1 && 1 >= LBLO) stage_one<P, 1, 1>(v, base, tw);
        if (LBHI >= 0 && 0 >= LBLO) stage_one<P, 0, 1>(v, base, tw);
    } else {
        if (LBLO <= 0 && 0 <= LBHI) stage_one<P, 0, 0>(v, base, tw);
        if (LBLO <= 1 && 1 <= LBHI) stage_one<P, 1, 0>(v, base, tw);
        if (LBLO <= 2 && 2 <= LBHI) stage_one<P, 2, 0>(v, base, tw);
        if (LBLO <= 3 && 3 <= LBHI) stage_one<P, 3, 0>(v, base, tw);
    }
}

extern __shared__ float2 smm[];
// layout (float2 units): [0..8191] exchange, [8192..12287] twiddles,
// [12288..12289] bin broadcast -> 98320 bytes total

__global__ void __launch_bounds__(512) fft_kernel(const float* __restrict__ x) {
    float2* sm = smm;
    float2* tw = smm + T_LEN;
    float2* bc = smm + T_LEN + HALF;
    const int tid = threadIdx.x;

    for (int t = tid; t < HALF; t += 512) {
        float s, c;
        sincosf(-6.283185307179586e0f * (float)t / (float)T_LEN, &s, &c);
        tw[t] = make_float2(c, s);
    }

    const int baseA = tid;                                  // P=9
    const int baseB = ((tid >> 5) << 9) + (tid & 31);       // P=5
    const int baseC = ((tid >> 1) << 5) + (tid & 1);        // P=1
    const int baseD = tid << 4;                             // P=0
    const int baseE = ((tid >> 4) << 8) + (tid & 15);       // P=4
    const int baseF = ((tid >> 8) << 12) + (tid & 255);     // P=8

    const float* __restrict__ xr = x + (size_t)blockIdx.x * 2 * T_LEN;
    float2 v[16];
    float x1s[16], x2s[16];
#pragma unroll
    for (int r = 0; r < 16; r++) {
        const int t = tid + (r << 9);
        float a = xr[t], b = xr[T_LEN + t];
        v[r] = make_float2(a, b);
        x1s[r] = a; x2s[r] = b;
    }
    __syncthreads();   // tw ready

    // ---- forward DIF: s = 12..0 (13 stages) ----
    stages<9, 1, 0, 3>(v, baseA, tw);
#pragma unroll
    for (int r = 0; r < 16; r++) sm[swz(baseA + (r << 9))] = v[r];
    __syncthreads();
#pragma unroll
    for (int r = 0; r < 16; r++) v[r] = sm[swz(baseB + (r << 5))];
    __syncthreads();
    stages<5, 1, 0, 3>(v, baseB, tw);
#pragma unroll
    for (int r = 0; r < 16; r++) sm[swz(baseB + (r << 5))] = v[r];
    __syncthreads();
#pragma unroll
    for (int r = 0; r < 16; r++) v[r] = sm[swz(baseC + (r << 1))];
    __syncthreads();
    stages<1, 1, 0, 3>(v, baseC, tw);
#pragma unroll
    for (int r = 0; r < 16; r++) sm[swz(baseC + (r << 1))] = v[r];
    __syncthreads();
#pragma unroll
    for (int r = 0; r < 16; r++) v[r] = sm[swz(baseD + r)];
    __syncthreads();
    stages<0, 1, 0, 0>(v, baseD, tw);       // fwd s=0 -> Z bit-reversed

    if (tid == 0) { bc[0] = v[0]; bc[1] = v[1]; }

    // Mask odd + inverse stage 0 fuse to a copy.
#pragma unroll
    for (int r = 0; r < 16; r += 2) v[r + 1] = v[r];

    stages<0, 0, 1, 3>(v, baseD, tw);       // s = 1..3
#pragma unroll
    for (int r = 0; r < 16; r++) sm[swz(baseD + r)] = v[r];
    __syncthreads();
#pragma unroll
    for (int r = 0; r < 16; r++) v[r] = sm[swz(baseE + (r << 4))];
    __syncthreads();
    stages<4, 0, 0, 3>(v, baseE, tw);       // s = 4..7
#pragma unroll
    for (int r = 0; r < 16; r++) sm[swz(baseE + (r << 4))] = v[r];
    __syncthreads();
#pragma unroll
    for (int r = 0; r < 16; r++) v[r] = sm[swz(baseF + (r << 8))];
    __syncthreads();
    stages<8, 0, 0, 3>(v, baseF, tw);       // s = 8..11
#pragma unroll
    for (int r = 0; r < 16; r++) sm[swz(baseF + (r << 8))] = v[r];
    __syncthreads();
#pragma unroll
    for (int r = 0; r < 16; r++) v[r] = sm[swz(baseA + (r << 9))];
    __syncthreads();
    stages<9, 0, 3, 3>(v, baseA, tw);       // s = 12 -> natural order

    const float2 Z0 = bc[0];
    const float2 Z1 = bc[1];
    const float par = (tid & 1) ? -1.0f : 1.0f;
    const float Nf = (float)T_LEN;
    const float b1 = Z0.x - Z1.x * par;
    const float b2 = Z0.y - Z1.y * par;
    const size_t row0 = (size_t)blockIdx.x * 2 * T_LEN;
#pragma unroll
    for (int r = 0; r < 16; r++) {
        const int t = tid + (r << 9);
        float2 U = v[r];
        float R1 = fmaf(Nf, x1s[r], b1);
        float R2 = fmaf(Nf, x2s[r], b2);
        float I1 = 2.0f * U.y - R2;
        float I2 = R1 - 2.0f * U.x;

        float m1 = R1 * R1 + I1 * I1;
        float c1, s1;
        if (m1 > 0.0f) { float iv = rsqrtf(m1); c1 = R1 * iv; s1 = I1 * iv; }
        else           { c1 = 1.0f; s1 = 0.0f; }
        float m2 = R2 * R2 + I2 * I2;
        float c2, s2;
        if (m2 > 0.0f) { float iv = rsqrtf(m2); c2 = R2 * iv; s2 = I2 * iv; }
        else           { c2 = 1.0f; s2 = 0.0f; }

        g_c[row0 + t]         = __uint_as_float(f2tf32(c1));
        g_s[row0 + t]         = __uint_as_float(f2tf32(s1));
        g_c[row0 + T_LEN + t] = __uint_as_float(f2tf32(c2));
        g_s[row0 + T_LEN + t] = __uint_as_float(f2tf32(s2));
    }
}

// ===========================================================================
// Kernel 2: tf32 single-chain Gram via mma.sync.m16n8k8 (R11, unchanged).
// ===========================================================================
extern __shared__ __align__(128) char gsm[];   // 2 * BUFB = 73728 B

__global__ void __launch_bounds__(256, 2) gram_tf32() {
    const int tid  = threadIdx.x;
    const int wid  = tid >> 5;
    const int lane = tid & 31;
    const int ks   = blockIdx.x;
    const int q    = blockIdx.y;
    const int b    = blockIdx.z;
    const bool diag = (q < 2);

    const float* __restrict__ srcA = (q == 0) ? g_c : g_s;
    const float* __restrict__ srcB = (q == 1) ? g_s : g_c;

    const uint32_t sb = smem_u32(gsm);
    const size_t k0 = (size_t)ks * (T_LEN / KSPLIT);

    const int qi  = tid & 7;
    const int r32 = tid >> 3;
    const int npass = diag ? 4 : 8;

    const float* psrc[8]; uint32_t pdst[8];
#pragma unroll
    for (int p = 0; p < 8; p++) {
        const int row = r32 + (p & 3) * 32;
        const float* srcm = (p < 4) ? srcA : srcB;
        psrc[p] = srcm + (size_t)(b * CH + row) * T_LEN + k0 + qi * 4;
        pdst[p] = (uint32_t)((p < 4 ? 0 : BOFF) + row * ROWB + qi * 16);
    }

    auto load_chunk = [&](int c) {
        const uint32_t bufb = sb + (uint32_t)((c & 1) * BUFB);
        const int kofs = c * KC;
#pragma unroll
        for (int p = 0; p < 8; p++) {
            if (p >= npass) break;
            cp16(bufb + pdst[p], psrc[p] + kofs);
        }
        CP_COMMIT();
    };

    const int mrow0 = (wid >> 2) * 64;
    const int ncol0 = (wid & 3) * 32;
    const uint32_t bOfs = diag ? 0u : (uint32_t)BOFF;

    float acc[4][4][4];
#pragma unroll
    for (int mt = 0; mt < 4; mt++)
#pragma unroll
        for (int nt = 0; nt < 4; nt++)
#pragma unroll
            for (int e = 0; e < 4; e++) acc[mt][nt][e] = 0.0f;

    const int lg = lane >> 2;
    const int lk = lane & 3;

    load_chunk(0);
    for (int c = 0; c < NCHUNK; c++) {
        if (c + 1 < NCHUNK) { load_chunk(c + 1); CP_WAIT1(); }
        else                { CP_WAIT0(); }
        __syncthreads();

        const uint32_t bufb = sb + (uint32_t)((c & 1) * BUFB);
#pragma unroll
        for (int kstep = 0; kstep < KC / 8; kstep++) {
            const uint32_t kb = (uint32_t)(kstep * 32 + lk * 4);
            uint32_t bfr[4][2];
#pragma unroll
            for (int nt = 0; nt < 4; nt++) {
                const uint32_t ba =
                    bufb + bOfs + (uint32_t)((ncol0 + nt * 8 + lg) * ROWB) + kb;
                bfr[nt][0] = lds32(ba);
                bfr[nt][1] = lds32(ba + 16);
            }
#pragma unroll
            for (int mt = 0; mt < 4; mt++) {
                const uint32_t aa =
                    bufb + (uint32_t)((mrow0 + mt * 16 + lg) * ROWB) + kb;
                uint32_t af[4];
                af[0] = lds32(aa);
                af[1] = lds32(aa + 8 * ROWB);
                af[2] = lds32(aa + 16);
                af[3] = lds32(aa + 8 * ROWB + 16);
#pragma unroll
                for (int nt = 0; nt < 4; nt++)
                    mma_tf32(acc[mt][nt], af, bfr[nt]);
            }
        }
        __syncthreads();
    }

    float* __restrict__ G =
        g_gram + ((size_t)((ks * BATCH + b) * 3 + q)) * (CH * CH);
    const int r0 = lane >> 2;
    const int c0 = (lane & 3) * 2;
#pragma unroll
    for (int mt = 0; mt < 4; mt++) {
        const int row = mrow0 + mt * 16 + r0;
#pragma unroll
        for (int nt = 0; nt < 4; nt++) {
            const int col = ncol0 + nt * 8 + c0;
            *(float2*)(G + row * CH + col) =
                make_float2(acc[mt][nt][0], acc[mt][nt][1]);
            *(float2*)(G + (row + 8) * CH + col) =
                make_float2(acc[mt][nt][2], acc[mt][nt][3]);
        }
    }
}

// ===========================================================================
// Kernel 3: tiled symmetric finalize.
// One block per (batch, upper 32x32 tile pair). All gram reads coalesced;
// SC-transpose and the mirror output write staged through smem.
// ===========================================================================
__global__ void __launch_bounds__(256) finalize_kernel(float* __restrict__ out) {
    const int b    = blockIdx.x;
    const int pair = blockIdx.y;               // 0..9 upper-triangle tile pairs
    int ti, tj;
    if (pair < 4)      { ti = 0; tj = pair; }
    else if (pair < 7) { ti = 1; tj = pair - 3; }
    else if (pair < 9) { ti = 2; tj = pair - 5; }
    else               { ti = 3; tj = 3; }

    const int r = threadIdx.x >> 5;            // 0..7
    const int c = threadIdx.x & 31;

    __shared__ float Tb[32][33];               // SC(tj,ti) tile for transpose
    __shared__ float Pv[32][33];               // plv tile for mirrored write

    float re[4]  = {0.0f, 0.0f, 0.0f, 0.0f};
    float imA[4] = {0.0f, 0.0f, 0.0f, 0.0f};
    float imB[4] = {0.0f, 0.0f, 0.0f, 0.0f};

    for (int ks = 0; ks < KSPLIT; ks++) {
        const float* __restrict__ base =
            g_gram + ((size_t)((ks * BATCH + b) * 3)) * CHCH;
#pragma unroll
        for (int k = 0; k < 4; k++) {
            const int a  = r + k * 8;
            const int ij = (ti * 32 + a) * CH + tj * 32 + c;
            const int ji = (tj * 32 + a) * CH + ti * 32 + c;
            re[k]  += base[ij] + base[CHCH + ij];          // CC + SS
            imA[k] += base[2 * CHCH + ij];                 // SC(i,j)
            imB[k] += base[2 * CHCH + ji];                 // SC(j,i) tile
        }
    }
#pragma unroll
    for (int k = 0; k < 4; k++) Tb[r + k * 8][c] = imB[k];
    __syncthreads();

#pragma unroll
    for (int k = 0; k < 4; k++) {
        const int a = r + k * 8;
        const float im = imA[k] - Tb[c][a];                // SC_ij - SC_ji
        const float plv = sqrtf(re[k] * re[k] + im * im) * (1.0f / (float)T_LEN);
        out[(b << 14) + (ti * 32 + a) * CH + tj * 32 + c] = plv;
        Pv[a][c] = plv;
    }
    __syncthreads();

    if (ti != tj) {
#pragma unroll
        for (int k = 0; k < 4; k++) {
            const int a = r + k * 8;                       // row within tj tile
            out[(b << 14) + (tj * 32 + a) * CH + ti * 32 + c] = Pv[c][a];
        }
    }
}

// ===========================================================================
extern "C" void kernel_launch(void* const* d_in, const int* in_sizes, int n_in,
                              void* d_out, int out_size) {
    const float* x = (const float*)d_in[0];
    float* out = (float*)d_out;

    const int fft_smem = (T_LEN + HALF + 2) * (int)sizeof(float2); // 98320
    cudaFuncSetAttribute(fft_kernel, cudaFuncAttributeMaxDynamicSharedMemorySize,
                         fft_smem);
    cudaFuncSetAttribute(gram_tf32, cudaFuncAttributeMaxDynamicSharedMemorySize,
                         2 * BUFB);

    fft_kernel<<<NSIG / 2, 512, fft_smem>>>(x);
    gram_tf32<<<dim3(KSPLIT, 3, BATCH), 256, 2 * BUFB>>>();
    finalize_kernel<<<dim3(BATCH, 10), 256>>>(out);
}

// round 17
// speedup vs baseline: 1.0581x; 1.0581x over previous
#include <cuda_runtime.h>
#include <math.h>
#include <stdint.h>

#define T_LEN 8192
#define HALF  4096
#define CH    128
#define BATCH 16
#define NSIG  (BATCH * CH)

#define KSPLIT 16
#define KC     32                          // fp32 per chunk = 128 B rows
#define NCHUNK ((T_LEN / KSPLIT) / KC)     // 16
#define ROWB   144                         // 128B data + 16B pad (conflict-free)
#define BOFF   (128 * ROWB)                // 18432
#define BUFB   (2 * 128 * ROWB)            // 36864 per buffer

// Scratch (alloc-free rule: __device__ globals)
__device__ float g_c[(size_t)BATCH * CH * T_LEN];             // cos(phase): 64 MB
__device__ float g_s[(size_t)BATCH * CH * T_LEN];             // sin(phase): 64 MB
__device__ float g_gram[(size_t)KSPLIT * BATCH * 3 * CH * CH];// tiles: 50 MB

// ===========================================================================
// PTX helpers
// ===========================================================================
__device__ __forceinline__ uint32_t smem_u32(const void* p) {
    uint32_t a;
    asm("{ .reg .u64 t; cvta.to.shared.u64 t, %1; cvt.u32.u64 %0, t; }"
        : "=r"(a) : "l"(p));
    return a;
}
__device__ __forceinline__ void mma_tf32(float* d, const uint32_t* a,
                                         const uint32_t* b) {
    asm volatile(
        "mma.sync.aligned.m16n8k8.row.col.f32.tf32.tf32.f32 "
        "{%0,%1,%2,%3}, {%4,%5,%6,%7}, {%8,%9}, {%0,%1,%2,%3};"
        : "+f"(d[0]), "+f"(d[1]), "+f"(d[2]), "+f"(d[3])
        : "r"(a[0]), "r"(a[1]), "r"(a[2]), "r"(a[3]), "r"(b[0]), "r"(b[1]));
}
__device__ __forceinline__ void cp16(uint32_t smem, const void* g) {
    asm volatile("cp.async.cg.shared.global [%0], [%1], 16;"
                 :: "r"(smem), "l"(g) : "memory");
}
#define CP_COMMIT() asm volatile("cp.async.commit_group;" ::: "memory")
#define CP_WAIT1()  asm volatile("cp.async.wait_group 1;" ::: "memory")
#define CP_WAIT0()  asm volatile("cp.async.wait_group 0;" ::: "memory")
__device__ __forceinline__ uint32_t lds32(uint32_t addr) {
    uint32_t v;
    asm volatile("ld.shared.b32 %0, [%1];" : "=r"(v) : "r"(addr));
    return v;
}
__device__ __forceinline__ uint32_t f2tf32(float f) {
    uint32_t u;
    asm("cvt.rna.tf32.f32 %0, %1;" : "=r"(u) : "f"(f));
    return u;
}

// ===========================================================================
// Kernel 1: two-channel real-packed FFT, single inverse chain (R15, unchanged)
// ===========================================================================
__device__ __forceinline__ int swz(int i) { return i ^ ((i >> 5) & 31); }

template<int P, int LB, int FWD>
__device__ __forceinline__ void stage_one(float2 v[16], int base,
                                          const float2* __restrict__ tw) {
    const int s  = P + LB;
    const int bm = base & ((1 << s) - 1);
    float2 wc[(LB < 3) ? (1 << LB) : 1];
    if (LB < 3) {
#pragma unroll
        for (int q = 0; q < (1 << LB); q++)
            wc[q] = tw[(bm + (q << P)) << (12 - s)];
    }
#pragma unroll
    for (int rr = 0; rr < 16; rr++) {
        if ((rr >> LB) & 1) continue;
        const int r1 = rr | (1 << LB);
        float2 w;
        if (LB < 3) w = wc[rr & ((1 << LB) - 1)];
        else        w = tw[(bm + ((rr & 7) << P)) << (12 - s)];
        float2 a = v[rr], b = v[r1];
        if (FWD) {
            v[rr] = make_float2(a.x + b.x, a.y + b.y);
            float2 d = make_float2(a.x - b.x, a.y - b.y);
            v[r1] = make_float2(d.x * w.x - d.y * w.y, d.x * w.y + d.y * w.x);
        } else {
            float2 tt = make_float2(b.x * w.x + b.y * w.y, b.y * w.x - b.x * w.y);
            v[rr] = make_float2(a.x + tt.x, a.y + tt.y);
            v[r1] = make_float2(a.x - tt.x, a.y - tt.y);
        }
    }
}

template<int P, int FWD, int LBLO, int LBHI>
__device__ __forceinline__ void stages(float2 v[16], int base,
                                       const float2* __restrict__ tw) {
    if (FWD) {
        if (LBHI >= 3 && 3 >= LBLO) stage_one<P, 3, 1>(v, base, tw);
        if (LBHI >= 2 && 2 >= LBLO) stage_one<P, 2, 1>(v, base, tw);
        if (LBHI >= 1 && 1 >= LBLO) stage_one<P, 1, 1>(v, base, tw);
        if (LBHI >= 0 && 0 >= LBLO) stage_one<P, 0, 1>(v, base, tw);
    } else {
        if (LBLO <= 0 && 0 <= LBHI) stage_one<P, 0, 0>(v, base, tw);
        if (LBLO <= 1 && 1 <= LBHI) stage_one<P, 1, 0>(v, base, tw);
        if (LBLO <= 2 && 2 <= LBHI) stage_one<P, 2, 0>(v, base, tw);
        if (LBLO <= 3 && 3 <= LBHI) stage_one<P, 3, 0>(v, base, tw);
    }
}

extern __shared__ float2 smm[];
// layout (float2 units): [0..8191] exchange, [8192..12287] twiddles,
// [12288..12289] bin broadcast -> 98320 bytes total

__global__ void __launch_bounds__(512) fft_kernel(const float* __restrict__ x) {
    float2* sm = smm;
    float2* tw = smm + T_LEN;
    float2* bc = smm + T_LEN + HALF;
    const int tid = threadIdx.x;

    for (int t = tid; t < HALF; t += 512) {
        float s, c;
        sincosf(-6.283185307179586e0f * (float)t / (float)T_LEN, &s, &c);
        tw[t] = make_float2(c, s);
    }

    const int baseA = tid;                                  // P=9
    const int baseB = ((tid >> 5) << 9) + (tid & 31);       // P=5
    const int baseC = ((tid >> 1) << 5) + (tid & 1);        // P=1
    const int baseD = tid << 4;                             // P=0
    const int baseE = ((tid >> 4) << 8) + (tid & 15);       // P=4
    const int baseF = ((tid >> 8) << 12) + (tid & 255);     // P=8

    const float* __restrict__ xr = x + (size_t)blockIdx.x * 2 * T_LEN;
    float2 v[16];
    float x1s[16], x2s[16];
#pragma unroll
    for (int r = 0; r < 16; r++) {
        const int t = tid + (r << 9);
        float a = xr[t], b = xr[T_LEN + t];
        v[r] = make_float2(a, b);
        x1s[r] = a; x2s[r] = b;
    }
    __syncthreads();   // tw ready

    // ---- forward DIF: s = 12..0 (13 stages) ----
    stages<9, 1, 0, 3>(v, baseA, tw);
#pragma unroll
    for (int r = 0; r < 16; r++) sm[swz(baseA + (r << 9))] = v[r];
    __syncthreads();
#pragma unroll
    for (int r = 0; r < 16; r++) v[r] = sm[swz(baseB + (r << 5))];
    __syncthreads();
    stages<5, 1, 0, 3>(v, baseB, tw);
#pragma unroll
    for (int r = 0; r < 16; r++) sm[swz(baseB + (r << 5))] = v[r];
    __syncthreads();
#pragma unroll
    for (int r = 0; r < 16; r++) v[r] = sm[swz(baseC + (r << 1))];
    __syncthreads();
    stages<1, 1, 0, 3>(v, baseC, tw);
#pragma unroll
    for (int r = 0; r < 16; r++) sm[swz(baseC + (r << 1))] = v[r];
    __syncthreads();
#pragma unroll
    for (int r = 0; r < 16; r++) v[r] = sm[swz(baseD + r)];
    __syncthreads();
    stages<0, 1, 0, 0>(v, baseD, tw);       // fwd s=0 -> Z bit-reversed

    if (tid == 0) { bc[0] = v[0]; bc[1] = v[1]; }

    // Mask odd + inverse stage 0 fuse to a copy.
#pragma unroll
    for (int r = 0; r < 16; r += 2) v[r + 1] = v[r];

    stages<0, 0, 1, 3>(v, baseD, tw);       // s = 1..3
#pragma unroll
    for (int r = 0; r < 16; r++) sm[swz(baseD + r)] = v[r];
    __syncthreads();
#pragma unroll
    for (int r = 0; r < 16; r++) v[r] = sm[swz(baseE + (r << 4))];
    __syncthreads();
    stages<4, 0, 0, 3>(v, baseE, tw);       // s = 4..7
#pragma unroll
    for (int r = 0; r < 16; r++) sm[swz(baseE + (r << 4))] = v[r];
    __syncthreads();
#pragma unroll
    for (int r = 0; r < 16; r++) v[r] = sm[swz(baseF + (r << 8))];
    __syncthreads();
    stages<8, 0, 0, 3>(v, baseF, tw);       // s = 8..11
#pragma unroll
    for (int r = 0; r < 16; r++) sm[swz(baseF + (r << 8))] = v[r];
    __syncthreads();
#pragma unroll
    for (int r = 0; r < 16; r++) v[r] = sm[swz(baseA + (r << 9))];
    __syncthreads();
    stages<9, 0, 3, 3>(v, baseA, tw);       // s = 12 -> natural order

    const float2 Z0 = bc[0];
    const float2 Z1 = bc[1];
    const float par = (tid & 1) ? -1.0f : 1.0f;
    const float Nf = (float)T_LEN;
    const float b1 = Z0.x - Z1.x * par;
    const float b2 = Z0.y - Z1.y * par;
    const size_t row0 = (size_t)blockIdx.x * 2 * T_LEN;
#pragma unroll
    for (int r = 0; r < 16; r++) {
        const int t = tid + (r << 9);
        float2 U = v[r];
        float R1 = fmaf(Nf, x1s[r], b1);
        float R2 = fmaf(Nf, x2s[r], b2);
        float I1 = 2.0f * U.y - R2;
        float I2 = R1 - 2.0f * U.x;

        float m1 = R1 * R1 + I1 * I1;
        float c1, s1;
        if (m1 > 0.0f) { float iv = rsqrtf(m1); c1 = R1 * iv; s1 = I1 * iv; }
        else           { c1 = 1.0f; s1 = 0.0f; }
        float m2 = R2 * R2 + I2 * I2;
        float c2, s2;
        if (m2 > 0.0f) { float iv = rsqrtf(m2); c2 = R2 * iv; s2 = I2 * iv; }
        else           { c2 = 1.0f; s2 = 0.0f; }

        g_c[row0 + t]         = __uint_as_float(f2tf32(c1));
        g_s[row0 + t]         = __uint_as_float(f2tf32(s1));
        g_c[row0 + T_LEN + t] = __uint_as_float(f2tf32(c2));
        g_s[row0 + T_LEN + t] = __uint_as_float(f2tf32(s2));
    }
}

// ===========================================================================
// Kernel 2: tf32 single-chain Gram via mma.sync.m16n8k8.
// GRID REORDER vs R15: q is now the fastest-varying block index, so the
// three q-variants of the same (ks,b) run concurrently and share their
// 512 KB input slice through L2 (halves DRAM reads).
// ===========================================================================
extern __shared__ __align__(128) char gsm[];   // 2 * BUFB = 73728 B

__global__ void __launch_bounds__(256, 2) gram_tf32() {
    const int tid  = threadIdx.x;
    const int wid  = tid >> 5;
    const int lane = tid & 31;
    const int q    = blockIdx.x;               // 0=CC 1=SS 2=SC (fastest)
    const int ks   = blockIdx.y;
    const int b    = blockIdx.z;
    const bool diag = (q < 2);

    const float* __restrict__ srcA = (q == 0) ? g_c : g_s;
    const float* __restrict__ srcB = (q == 1) ? g_s : g_c;

    const uint32_t sb = smem_u32(gsm);
    const size_t k0 = (size_t)ks * (T_LEN / KSPLIT);

    const int qi  = tid & 7;
    const int r32 = tid >> 3;
    const int npass = diag ? 4 : 8;

    const float* psrc[8]; uint32_t pdst[8];
#pragma unroll
    for (int p = 0; p < 8; p++) {
        const int row = r32 + (p & 3) * 32;
        const float* srcm = (p < 4) ? srcA : srcB;
        psrc[p] = srcm + (size_t)(b * CH + row) * T_LEN + k0 + qi * 4;
        pdst[p] = (uint32_t)((p < 4 ? 0 : BOFF) + row * ROWB + qi * 16);
    }

    auto load_chunk = [&](int c) {
        const uint32_t bufb = sb + (uint32_t)((c & 1) * BUFB);
        const int kofs = c * KC;
#pragma unroll
        for (int p = 0; p < 8; p++) {
            if (p >= npass) break;
            cp16(bufb + pdst[p], psrc[p] + kofs);
        }
        CP_COMMIT();
    };

    const int mrow0 = (wid >> 2) * 64;
    const int ncol0 = (wid & 3) * 32;
    const uint32_t bOfs = diag ? 0u : (uint32_t)BOFF;

    float acc[4][4][4];
#pragma unroll
    for (int mt = 0; mt < 4; mt++)
#pragma unroll
        for (int nt = 0; nt < 4; nt++)
#pragma unroll
            for (int e = 0; e < 4; e++) acc[mt][nt][e] = 0.0f;

    const int lg = lane >> 2;
    const int lk = lane & 3;

    load_chunk(0);
    for (int c = 0; c < NCHUNK; c++) {
        if (c + 1 < NCHUNK) { load_chunk(c + 1); CP_WAIT1(); }
        else                { CP_WAIT0(); }
        __syncthreads();

        const uint32_t bufb = sb + (uint32_t)((c & 1) * BUFB);
#pragma unroll
        for (int kstep = 0; kstep < KC / 8; kstep++) {
            const uint32_t kb = (uint32_t)(kstep * 32 + lk * 4);
            uint32_t bfr[4][2];
#pragma unroll
            for (int nt = 0; nt < 4; nt++) {
                const uint32_t ba =
                    bufb + bOfs + (uint32_t)((ncol0 + nt * 8 + lg) * ROWB) + kb;
                bfr[nt][0] = lds32(ba);
                bfr[nt][1] = lds32(ba + 16);
            }
#pragma unroll
            for (int mt = 0; mt < 4; mt++) {
                const uint32_t aa =
                    bufb + (uint32_t)((mrow0 + mt * 16 + lg) * ROWB) + kb;
                uint32_t af[4];
                af[0] = lds32(aa);
                af[1] = lds32(aa + 8 * ROWB);
                af[2] = lds32(aa + 16);
                af[3] = lds32(aa + 8 * ROWB + 16);
#pragma unroll
                for (int nt = 0; nt < 4; nt++)
                    mma_tf32(acc[mt][nt], af, bfr[nt]);
            }
        }
        __syncthreads();
    }

    float* __restrict__ G =
        g_gram + ((size_t)((ks * BATCH + b) * 3 + q)) * (CH * CH);
    const int r0 = lane >> 2;
    const int c0 = (lane & 3) * 2;
#pragma unroll
    for (int mt = 0; mt < 4; mt++) {
        const int row = mrow0 + mt * 16 + r0;
#pragma unroll
        for (int nt = 0; nt < 4; nt++) {
            const int col = ncol0 + nt * 8 + c0;
            *(float2*)(G + row * CH + col) =
                make_float2(acc[mt][nt][0], acc[mt][nt][1]);
            *(float2*)(G + (row + 8) * CH + col) =
                make_float2(acc[mt][nt][2], acc[mt][nt][3]);
        }
    }
}

// ===========================================================================
// Kernel 3: combine K-splits; Re = CC+SS, Im = SC_ij - SC_ji; PLV = |.|/T.
// (R15 flat version — the tiled variant regressed.)
// ===========================================================================
__global__ void finalize_kernel(float* __restrict__ out) {
    const int idx = blockIdx.x * blockDim.x + threadIdx.x;
    if (idx >= BATCH * CH * CH) return;
    const int b  = idx >> 14;
    const int ij = idx & 16383;
    const int i  = ij >> 7;
    const int j  = ij & 127;
    float re = 0.0f, im = 0.0f;
#pragma unroll
    for (int ks = 0; ks < KSPLIT; ks++) {
        const float* __restrict__ base =
            g_gram + ((size_t)((ks * BATCH + b) * 3)) * (CH * CH);
        re += base[ij] + base[CH * CH + ij];                       // CC + SS
        im += base[2 * CH * CH + i * CH + j]
            - base[2 * CH * CH + j * CH + i];                      // SC - SC^T
    }
    out[idx] = sqrtf(re * re + im * im) * (1.0f / (float)T_LEN);
}

// ===========================================================================
extern "C" void kernel_launch(void* const* d_in, const int* in_sizes, int n_in,
                              void* d_out, int out_size) {
    const float* x = (const float*)d_in[0];
    float* out = (float*)d_out;

    const int fft_smem = (T_LEN + HALF + 2) * (int)sizeof(float2); // 98320
    cudaFuncSetAttribute(fft_kernel, cudaFuncAttributeMaxDynamicSharedMemorySize,
                         fft_smem);
    cudaFuncSetAttribute(gram_tf32, cudaFuncAttributeMaxDynamicSharedMemorySize,
                         2 * BUFB);

    fft_kernel<<<NSIG / 2, 512, fft_smem>>>(x);
    gram_tf32<<<dim3(3, KSPLIT, BATCH), 256, 2 * BUFB>>>();
    finalize_kernel<<<(BATCH * CH * CH + 255) / 256, 256>>>(out);
}